// round 15
// baseline (speedup 1.0000x reference)
#include <cuda_runtime.h>
#include <cuda_bf16.h>
#include <cstdint>

// Problem constants
#define B_  4
#define T_  2048
#define E_  1024
#define H_  16
#define D_  64

#define M_TOTAL (B_ * T_)          // 8192
#define NQKV    (3 * H_ * D_)      // 3072

// ---------------------------------------------------------------------------
// Scratch (__device__ globals: allocation-free rule)
// ---------------------------------------------------------------------------
__device__ __nv_bfloat16 g_qh[B_ * H_ * T_ * D_];
__device__ __nv_bfloat16 g_ql[B_ * H_ * T_ * D_];
__device__ __nv_bfloat16 g_kh[B_ * H_ * T_ * D_];
__device__ __nv_bfloat16 g_kl[B_ * H_ * T_ * D_];
__device__ __nv_bfloat16 g_vh[B_ * H_ * T_ * D_];
__device__ __nv_bfloat16 g_vl[B_ * H_ * T_ * D_];

__device__ __nv_bfloat16 g_xh[M_TOTAL * E_];
__device__ __nv_bfloat16 g_xl[M_TOTAL * E_];
__device__ __nv_bfloat16 g_bqh[NQKV * E_];
__device__ __nv_bfloat16 g_bql[NQKV * E_];
__device__ __nv_bfloat16 g_wph[E_ * E_];
__device__ __nv_bfloat16 g_wpl[E_ * E_];
__device__ __nv_bfloat16 g_ath[M_TOTAL * E_];
__device__ __nv_bfloat16 g_atl[M_TOTAL * E_];

// ---------------------------------------------------------------------------
// Helpers
// ---------------------------------------------------------------------------
__device__ __forceinline__ void mma16816(float c[4], const uint32_t a[4],
                                         uint32_t b0, uint32_t b1) {
    asm volatile(
        "mma.sync.aligned.m16n8k16.row.col.f32.bf16.bf16.f32 "
        "{%0,%1,%2,%3}, {%4,%5,%6,%7}, {%8,%9}, {%0,%1,%2,%3};"
        : "+f"(c[0]), "+f"(c[1]), "+f"(c[2]), "+f"(c[3])
        : "r"(a[0]), "r"(a[1]), "r"(a[2]), "r"(a[3]), "r"(b0), "r"(b1));
}

__device__ __forceinline__ void ldsm4(uint32_t r[4], const void* p) {
    uint32_t a = (uint32_t)__cvta_generic_to_shared(p);
    asm volatile("ldmatrix.sync.aligned.m8n8.x4.shared.b16 {%0,%1,%2,%3}, [%4];"
                 : "=r"(r[0]), "=r"(r[1]), "=r"(r[2]), "=r"(r[3]) : "r"(a));
}

// pack two fp32 -> bf16x2 (lo in bits [0:16), hi in [16:32))
__device__ __forceinline__ uint32_t pack_bf16x2(float lo, float hi) {
    uint32_t r;
    asm("cvt.rn.bf16x2.f32 %0, %1, %2;" : "=r"(r) : "f"(hi), "f"(lo));
    return r;
}
__device__ __forceinline__ void split2(float v0, float v1, uint32_t& hp, uint32_t& lp) {
    hp = pack_bf16x2(v0, v1);
    float h0 = __uint_as_float(hp << 16);
    float h1 = __uint_as_float(hp & 0xFFFF0000u);
    lp = pack_bf16x2(v0 - h0, v1 - h1);
}

// ---------------------------------------------------------------------------
// Conversion kernels
// ---------------------------------------------------------------------------
__global__ __launch_bounds__(256) void conv_split4_kernel(
    const float* __restrict__ src, __nv_bfloat16* __restrict__ hi,
    __nv_bfloat16* __restrict__ lo, int n4)
{
    int i = blockIdx.x * 256 + threadIdx.x;
    if (i < n4) {
        float4 v = ((const float4*)src)[i];
        uint2 hp, lp;
        split2(v.x, v.y, hp.x, lp.x);
        split2(v.z, v.w, hp.y, lp.y);
        ((uint2*)hi)[i] = hp;
        ((uint2*)lo)[i] = lp;
    }
}

__global__ __launch_bounds__(256) void conv_wqkv_kernel(
    const float* __restrict__ Wq, const float* __restrict__ Wk, const float* __restrict__ Wv)
{
    __shared__ float tile[32][33];
    const int e0 = blockIdx.x * 32;
    const int d0 = blockIdx.y * 32;
    const int z  = blockIdx.z;
    const int which = z / H_, h = z % H_;
    const float* W = (which == 0) ? Wq : (which == 1) ? Wk : Wv;
    W += (size_t)h * E_ * D_;

    const int tx = threadIdx.x & 31, ty = threadIdx.x >> 5;
#pragma unroll
    for (int k = 0; k < 4; k++) {
        int e = e0 + ty + k * 8;
        tile[ty + k * 8][tx] = W[(size_t)e * D_ + d0 + tx];
    }
    __syncthreads();
    const int nbase = which * 1024 + h * 64;
#pragma unroll
    for (int k = 0; k < 4; k++) {
        int d = d0 + ty + k * 8;
        float v = tile[tx][ty + k * 8];
        __nv_bfloat16 hh = __float2bfloat16(v);
        size_t o = (size_t)(nbase + d) * E_ + e0 + tx;
        g_bqh[o] = hh;
        g_bql[o] = __float2bfloat16(v - __bfloat162float(hh));
    }
}

// ---------------------------------------------------------------------------
// Split-bf16 GEMM on mma.sync + ldmatrix fragment loads. KC=64, 2 CTAs/SM.
// Block tile 128x128, 8 warps (2x4), warp tile 64x32.  (R13 — proven 423us)
// ---------------------------------------------------------------------------
#define KC  64
#define LDT 72
#define TILE_E (128 * LDT)
#define GEMM_SMEM_BYTES (4 * TILE_E * 2)    // 72 KB

__global__ __launch_bounds__(256, 2) void gemm_mma_kernel(int mode, const float* __restrict__ bp,
                                                          float* __restrict__ out)
{
    extern __shared__ __nv_bfloat16 smx[];
    __nv_bfloat16* Ah = smx;
    __nv_bfloat16* Al = smx + TILE_E;
    __nv_bfloat16* Bh = smx + 2 * TILE_E;
    __nv_bfloat16* Bl = smx + 3 * TILE_E;

    const int tid  = threadIdx.x;
    const int wid  = tid >> 5;
    const int lane = tid & 31;
    const int wm = wid >> 2;
    const int wn = wid & 3;
    const int group = lane >> 2;
    const int tig   = lane & 3;

    // ldmatrix lane address components
    const int a_row = lane & 15;
    const int a_col = (lane >> 4) * 8;
    const int b_row = (lane & 7) + ((lane >> 4) << 3);
    const int b_col = ((lane >> 3) & 1) * 8;

    const int m0 = blockIdx.x * 128;
    const int n0 = blockIdx.y * 128;

    const __nv_bfloat16 *gAh, *gAl, *gBh, *gBl;
    if (mode == 0) { gAh = g_xh; gAl = g_xl; gBh = g_bqh; gBl = g_bql; }
    else           { gAh = g_ath; gAl = g_atl; gBh = g_wph; gBl = g_wpl; }

    float acc[4][4][4];
#pragma unroll
    for (int mi = 0; mi < 4; mi++)
#pragma unroll
        for (int ni = 0; ni < 4; ni++)
#pragma unroll
            for (int f = 0; f < 4; f++) acc[mi][ni][f] = 0.f;

    for (int e0 = 0; e0 < E_; e0 += KC) {
#pragma unroll
        for (int i = 0; i < 4; i++) {
            int idx = tid + i * 256;
            int r = idx >> 3, q = idx & 7;
            *(uint4*)(Ah + r * LDT + q * 8) = *(const uint4*)(gAh + (size_t)(m0 + r) * E_ + e0 + q * 8);
            *(uint4*)(Al + r * LDT + q * 8) = *(const uint4*)(gAl + (size_t)(m0 + r) * E_ + e0 + q * 8);
            *(uint4*)(Bh + r * LDT + q * 8) = *(const uint4*)(gBh + (size_t)(n0 + r) * E_ + e0 + q * 8);
            *(uint4*)(Bl + r * LDT + q * 8) = *(const uint4*)(gBl + (size_t)(n0 + r) * E_ + e0 + q * 8);
        }
        __syncthreads();

#pragma unroll
        for (int k0 = 0; k0 < KC; k0 += 16) {
            uint32_t ah[4][4], al[4][4];
#pragma unroll
            for (int mi = 0; mi < 4; mi++) {
                const size_t aoff = (size_t)(wm * 64 + mi * 16 + a_row) * LDT + k0 + a_col;
                ldsm4(ah[mi], Ah + aoff);
                ldsm4(al[mi], Al + aoff);
            }
            uint32_t bh4[2][4], bl4[2][4];
#pragma unroll
            for (int np = 0; np < 2; np++) {
                const size_t boff = (size_t)(wn * 32 + np * 16 + b_row) * LDT + k0 + b_col;
                ldsm4(bh4[np], Bh + boff);
                ldsm4(bl4[np], Bl + boff);
            }
#pragma unroll
            for (int ni = 0; ni < 4; ni++) {
                uint32_t bh0 = bh4[ni >> 1][(ni & 1) * 2];
                uint32_t bh1 = bh4[ni >> 1][(ni & 1) * 2 + 1];
                uint32_t bl0 = bl4[ni >> 1][(ni & 1) * 2];
                uint32_t bl1 = bl4[ni >> 1][(ni & 1) * 2 + 1];
#pragma unroll
                for (int mi = 0; mi < 4; mi++) {
                    mma16816(acc[mi][ni], ah[mi], bh0, bh1);
                    mma16816(acc[mi][ni], ah[mi], bl0, bl1);
                    mma16816(acc[mi][ni], al[mi], bh0, bh1);
                }
            }
        }
        __syncthreads();
    }

    // Epilogue
#pragma unroll
    for (int mi = 0; mi < 4; mi++) {
        int row0 = m0 + wm * 64 + mi * 16 + group;
#pragma unroll
        for (int ni = 0; ni < 4; ni++) {
            int nc = n0 + wn * 32 + ni * 8 + tig * 2;
            if (mode == 0) {
                const int which = nc >> 10;
                const int rem = nc & 1023;
                const int h = rem >> 6, d = rem & 63;
                __nv_bfloat16* bash = (which == 0) ? g_qh : (which == 1) ? g_kh : g_vh;
                __nv_bfloat16* basl = (which == 0) ? g_ql : (which == 1) ? g_kl : g_vl;
                const float sc = (which == 0) ? 0.125f : 1.0f;
#pragma unroll
                for (int half = 0; half < 2; half++) {
                    const int row = row0 + half * 8;
                    const int b = row >> 11, t = row & 2047;
                    float v0 = acc[mi][ni][half * 2] * sc;
                    float v1 = acc[mi][ni][half * 2 + 1] * sc;
                    uint32_t hp, lp;
                    split2(v0, v1, hp, lp);
                    size_t off = (((size_t)(b * H_ + h)) * T_ + t) * D_ + d;
                    *(uint32_t*)(bash + off) = hp;
                    *(uint32_t*)(basl + off) = lp;
                }
            } else {
                float2 bias = *(const float2*)(bp + nc);
                float2 v0 = make_float2(acc[mi][ni][0] + bias.x, acc[mi][ni][1] + bias.y);
                float2 v1 = make_float2(acc[mi][ni][2] + bias.x, acc[mi][ni][3] + bias.y);
                *(float2*)(out + (size_t)row0 * E_ + nc) = v0;
                *(float2*)(out + (size_t)(row0 + 8) * E_ + nc) = v1;
            }
        }
    }
}

// ---------------------------------------------------------------------------
// Flash attention on mma.sync, split-bf16, online softmax in registers.
// CTA: 128 q-rows of one (b,h); 8 warps x 16 rows. kv tiles of 64.
// R15: __launch_bounds__(256, 2) — 2 CTAs/SM (smem 34KB fits twice); the
// second CTA's MMA bursts cover this CTA's load/softmax phases.
// ---------------------------------------------------------------------------
#define LDK 72

__global__ __launch_bounds__(256, 2) void flash_mma_kernel()
{
    __shared__ __nv_bfloat16 Kh[64 * LDK];
    __shared__ __nv_bfloat16 Kl[64 * LDK];
    __shared__ uint32_t Vhl[64 * 64];   // packed (hi | lo<<16), word (d, kv^((d&3)<<3))

    const int tid  = threadIdx.x;
    const int wid  = tid >> 5;
    const int lane = tid & 31;
    const int g  = lane >> 2;
    const int tg = lane & 3;

    const int qt = blockIdx.x;
    const int h  = blockIdx.y;
    const int b  = blockIdx.z;
    const int bh = b * H_ + h;
    const int q0 = qt * 128;
    const int row_lo = q0 + wid * 16 + g;

    const __nv_bfloat16* gQh = g_qh + (size_t)bh * T_ * D_;
    const __nv_bfloat16* gQl = g_ql + (size_t)bh * T_ * D_;
    const __nv_bfloat16* gKh = g_kh + (size_t)bh * T_ * D_;
    const __nv_bfloat16* gKl = g_kl + (size_t)bh * T_ * D_;
    const __nv_bfloat16* gVh = g_vh + (size_t)bh * T_ * D_;
    const __nv_bfloat16* gVl = g_vl + (size_t)bh * T_ * D_;

    // Preload Q fragments (Q already scaled by 1/sqrt(D))
    uint32_t qh[4][4], ql[4][4];
#pragma unroll
    for (int ks = 0; ks < 4; ks++) {
        int c = ks * 16 + tg * 2;
        qh[ks][0] = *(const uint32_t*)(gQh + (size_t)row_lo * D_ + c);
        qh[ks][1] = *(const uint32_t*)(gQh + (size_t)(row_lo + 8) * D_ + c);
        qh[ks][2] = *(const uint32_t*)(gQh + (size_t)row_lo * D_ + c + 8);
        qh[ks][3] = *(const uint32_t*)(gQh + (size_t)(row_lo + 8) * D_ + c + 8);
        ql[ks][0] = *(const uint32_t*)(gQl + (size_t)row_lo * D_ + c);
        ql[ks][1] = *(const uint32_t*)(gQl + (size_t)(row_lo + 8) * D_ + c);
        ql[ks][2] = *(const uint32_t*)(gQl + (size_t)row_lo * D_ + c + 8);
        ql[ks][3] = *(const uint32_t*)(gQl + (size_t)(row_lo + 8) * D_ + c + 8);
    }

    float m0 = -1e30f, m1 = -1e30f, l0 = 0.f, l1 = 0.f;
    float o[8][4];
#pragma unroll
    for (int nd = 0; nd < 8; nd++)
#pragma unroll
        for (int f = 0; f < 4; f++) o[nd][f] = 0.f;

    const int ntiles = 2 * qt + 2;
    for (int j = 0; j < ntiles; j++) {
        const int kv0 = j * 64;
#pragma unroll
        for (int i = 0; i < 2; i++) {
            int idx = tid + i * 256;
            int r = idx >> 3, qd = idx & 7;
            *(uint4*)(Kh + r * LDK + qd * 8) =
                *(const uint4*)(gKh + (size_t)(kv0 + r) * D_ + qd * 8);
            *(uint4*)(Kl + r * LDK + qd * 8) =
                *(const uint4*)(gKl + (size_t)(kv0 + r) * D_ + qd * 8);
        }
#pragma unroll
        for (int i = 0; i < 2; i++) {
            int idx = tid + i * 256;
            int kv = idx & 63, dq = idx >> 6;
            uint4 vh = *(const uint4*)(gVh + (size_t)(kv0 + kv) * D_ + dq * 8);
            uint4 vl = *(const uint4*)(gVl + (size_t)(kv0 + kv) * D_ + dq * 8);
            const uint32_t* vhw = (const uint32_t*)&vh;
            const uint32_t* vlw = (const uint32_t*)&vl;
#pragma unroll
            for (int jj = 0; jj < 8; jj++) {
                uint32_t hv = vhw[jj >> 1], lv = vlw[jj >> 1];
                uint32_t packed = __byte_perm(hv, lv, (jj & 1) ? 0x7632 : 0x5410);
                int d = dq * 8 + jj;
                Vhl[d * 64 + (kv ^ ((jj & 3) << 3))] = packed;
            }
        }
        __syncthreads();

        // ---- S = Q K^T (split 3-MMA), scalar K fragment loads ----
        float s[8][4];
#pragma unroll
        for (int nf = 0; nf < 8; nf++)
#pragma unroll
            for (int f = 0; f < 4; f++) s[nf][f] = 0.f;
#pragma unroll
        for (int ks = 0; ks < 4; ks++) {
            int c = ks * 16 + tg * 2;
#pragma unroll
            for (int nf = 0; nf < 8; nf++) {
                int br = nf * 8 + g;
                uint32_t bh0 = *(const uint32_t*)(Kh + br * LDK + c);
                uint32_t bh1 = *(const uint32_t*)(Kh + br * LDK + c + 8);
                uint32_t bl0 = *(const uint32_t*)(Kl + br * LDK + c);
                uint32_t bl1 = *(const uint32_t*)(Kl + br * LDK + c + 8);
                mma16816(s[nf], qh[ks], bh0, bh1);
                mma16816(s[nf], qh[ks], bl0, bl1);
                mma16816(s[nf], ql[ks], bh0, bh1);
            }
        }

        // ---- causal mask ----
        if (j >= ntiles - 2) {
#pragma unroll
            for (int nf = 0; nf < 8; nf++) {
                int col = kv0 + nf * 8 + tg * 2;
                if (col > row_lo)     s[nf][0] = -1e30f;
                if (col + 1 > row_lo) s[nf][1] = -1e30f;
                if (col > row_lo + 8)     s[nf][2] = -1e30f;
                if (col + 1 > row_lo + 8) s[nf][3] = -1e30f;
            }
        }

        // ---- online softmax ----
        float mx0 = -1e30f, mx1 = -1e30f;
#pragma unroll
        for (int nf = 0; nf < 8; nf++) {
            mx0 = fmaxf(mx0, fmaxf(s[nf][0], s[nf][1]));
            mx1 = fmaxf(mx1, fmaxf(s[nf][2], s[nf][3]));
        }
        mx0 = fmaxf(mx0, __shfl_xor_sync(0xffffffff, mx0, 1));
        mx0 = fmaxf(mx0, __shfl_xor_sync(0xffffffff, mx0, 2));
        mx1 = fmaxf(mx1, __shfl_xor_sync(0xffffffff, mx1, 1));
        mx1 = fmaxf(mx1, __shfl_xor_sync(0xffffffff, mx1, 2));
        float mn0 = fmaxf(m0, mx0), mn1 = fmaxf(m1, mx1);
        float c0 = __expf(m0 - mn0), c1 = __expf(m1 - mn1);
        m0 = mn0; m1 = mn1;

        uint32_t ph[4][4], pl[4][4];
        float sum0 = 0.f, sum1 = 0.f;
#pragma unroll
        for (int nf = 0; nf < 8; nf++) {
            float p0 = __expf(s[nf][0] - mn0);
            float p1 = __expf(s[nf][1] - mn0);
            float p2 = __expf(s[nf][2] - mn1);
            float p3 = __expf(s[nf][3] - mn1);
            sum0 += p0 + p1;
            sum1 += p2 + p3;
            int ks = nf >> 1, rr = (nf & 1) * 2;
            split2(p0, p1, ph[ks][rr], pl[ks][rr]);
            split2(p2, p3, ph[ks][rr + 1], pl[ks][rr + 1]);
        }
        sum0 += __shfl_xor_sync(0xffffffff, sum0, 1);
        sum0 += __shfl_xor_sync(0xffffffff, sum0, 2);
        sum1 += __shfl_xor_sync(0xffffffff, sum1, 1);
        sum1 += __shfl_xor_sync(0xffffffff, sum1, 2);
        l0 = l0 * c0 + sum0;
        l1 = l1 * c1 + sum1;

#pragma unroll
        for (int nd = 0; nd < 8; nd++) {
            o[nd][0] *= c0; o[nd][1] *= c0;
            o[nd][2] *= c1; o[nd][3] *= c1;
        }

        // ---- O += P V (split 3-MMA) ----
#pragma unroll
        for (int ks = 0; ks < 4; ks++) {
            int kvA = ks * 16 + tg * 2;
            int sw = (g & 3) << 3;
#pragma unroll
            for (int nd = 0; nd < 8; nd++) {
                int d = nd * 8 + g;
                uint32_t u0 = Vhl[d * 64 + (kvA ^ sw)];
                uint32_t u1 = Vhl[d * 64 + ((kvA + 1) ^ sw)];
                uint32_t u2 = Vhl[d * 64 + ((kvA + 8) ^ sw)];
                uint32_t u3 = Vhl[d * 64 + ((kvA + 9) ^ sw)];
                uint32_t vh0 = __byte_perm(u0, u1, 0x5410);
                uint32_t vl0 = __byte_perm(u0, u1, 0x7632);
                uint32_t vh1 = __byte_perm(u2, u3, 0x5410);
                uint32_t vl1 = __byte_perm(u2, u3, 0x7632);
                mma16816(o[nd], ph[ks], vh0, vh1);
                mma16816(o[nd], ph[ks], vl0, vl1);
                mma16816(o[nd], pl[ks], vh0, vh1);
            }
        }
        __syncthreads();
    }

    // ---- epilogue ----
    float i0 = 1.f / l0, i1 = 1.f / l1;
#pragma unroll
    for (int nd = 0; nd < 8; nd++) {
        int dcol = h * 64 + nd * 8 + tg * 2;
        const int grow0 = b * T_ + row_lo;
        const int grow1 = grow0 + 8;
        uint32_t hp, lp;
        split2(o[nd][0] * i0, o[nd][1] * i0, hp, lp);
        *(uint32_t*)(g_ath + (size_t)grow0 * E_ + dcol) = hp;
        *(uint32_t*)(g_atl + (size_t)grow0 * E_ + dcol) = lp;
        split2(o[nd][2] * i1, o[nd][3] * i1, hp, lp);
        *(uint32_t*)(g_ath + (size_t)grow1 * E_ + dcol) = hp;
        *(uint32_t*)(g_atl + (size_t)grow1 * E_ + dcol) = lp;
    }
}

// ---------------------------------------------------------------------------
extern "C" void kernel_launch(void* const* d_in, const int* in_sizes, int n_in,
                              void* d_out, int out_size)
{
    const float* x  = (const float*)d_in[0];
    const float* Wq = (const float*)d_in[1];
    const float* Wk = (const float*)d_in[2];
    const float* Wv = (const float*)d_in[3];
    const float* Wp = (const float*)d_in[4];
    const float* bp = (const float*)d_in[5];
    float* out = (float*)d_out;

    cudaFuncSetAttribute(gemm_mma_kernel,
                         cudaFuncAttributeMaxDynamicSharedMemorySize, GEMM_SMEM_BYTES);

    __nv_bfloat16 *xh, *xl, *wph, *wpl;
    cudaGetSymbolAddress((void**)&xh,  g_xh);
    cudaGetSymbolAddress((void**)&xl,  g_xl);
    cudaGetSymbolAddress((void**)&wph, g_wph);
    cudaGetSymbolAddress((void**)&wpl, g_wpl);

    // 1) split-convert x and weights
    conv_split4_kernel<<<(M_TOTAL * E_ / 4 + 255) / 256, 256>>>(x, xh, xl, M_TOTAL * E_ / 4);
    conv_wqkv_kernel<<<dim3(E_ / 32, D_ / 32, 3 * H_), 256>>>(Wq, Wk, Wv);
    conv_split4_kernel<<<(E_ * E_ / 4 + 255) / 256, 256>>>(Wp, wph, wpl, E_ * E_ / 4);

    // 2) QKV projection -> split-bf16 q/k/v (Q pre-scaled)
    gemm_mma_kernel<<<dim3(M_TOTAL / 128, NQKV / 128), 256, GEMM_SMEM_BYTES>>>(0, nullptr, nullptr);

    // 3) causal flash attention on tensor cores -> g_ath/g_atl
    flash_mma_kernel<<<dim3(T_ / 128, H_, B_), 256>>>();

    // 4) output projection
    gemm_mma_kernel<<<dim3(M_TOTAL / 128, E_ / 128), 256, GEMM_SMEM_BYTES>>>(1, bp, out);
}

// round 16
// speedup vs baseline: 1.0752x; 1.0752x over previous
#include <cuda_runtime.h>
#include <cuda_bf16.h>
#include <cstdint>

// Problem constants
#define B_  4
#define T_  2048
#define E_  1024
#define H_  16
#define D_  64

#define M_TOTAL (B_ * T_)          // 8192
#define NQKV    (3 * H_ * D_)      // 3072

// ---------------------------------------------------------------------------
// Scratch (__device__ globals: allocation-free rule)
// ---------------------------------------------------------------------------
__device__ __nv_bfloat16 g_qh[B_ * H_ * T_ * D_];
__device__ __nv_bfloat16 g_ql[B_ * H_ * T_ * D_];
__device__ __nv_bfloat16 g_kh[B_ * H_ * T_ * D_];
__device__ __nv_bfloat16 g_kl[B_ * H_ * T_ * D_];
__device__ __nv_bfloat16 g_vh[B_ * H_ * T_ * D_];
__device__ __nv_bfloat16 g_vl[B_ * H_ * T_ * D_];

__device__ __nv_bfloat16 g_xh[M_TOTAL * E_];
__device__ __nv_bfloat16 g_xl[M_TOTAL * E_];
__device__ __nv_bfloat16 g_bqh[NQKV * E_];
__device__ __nv_bfloat16 g_bql[NQKV * E_];
__device__ __nv_bfloat16 g_wph[E_ * E_];
__device__ __nv_bfloat16 g_wpl[E_ * E_];
__device__ __nv_bfloat16 g_ath[M_TOTAL * E_];
__device__ __nv_bfloat16 g_atl[M_TOTAL * E_];

// ---------------------------------------------------------------------------
// Helpers
// ---------------------------------------------------------------------------
__device__ __forceinline__ void mma16816(float c[4], const uint32_t a[4],
                                         uint32_t b0, uint32_t b1) {
    asm volatile(
        "mma.sync.aligned.m16n8k16.row.col.f32.bf16.bf16.f32 "
        "{%0,%1,%2,%3}, {%4,%5,%6,%7}, {%8,%9}, {%0,%1,%2,%3};"
        : "+f"(c[0]), "+f"(c[1]), "+f"(c[2]), "+f"(c[3])
        : "r"(a[0]), "r"(a[1]), "r"(a[2]), "r"(a[3]), "r"(b0), "r"(b1));
}

__device__ __forceinline__ void ldsm4(uint32_t r[4], const void* p) {
    uint32_t a = (uint32_t)__cvta_generic_to_shared(p);
    asm volatile("ldmatrix.sync.aligned.m8n8.x4.shared.b16 {%0,%1,%2,%3}, [%4];"
                 : "=r"(r[0]), "=r"(r[1]), "=r"(r[2]), "=r"(r[3]) : "r"(a));
}
__device__ __forceinline__ void ldsm4t(uint32_t r[4], const void* p) {
    uint32_t a = (uint32_t)__cvta_generic_to_shared(p);
    asm volatile("ldmatrix.sync.aligned.m8n8.x4.trans.shared.b16 {%0,%1,%2,%3}, [%4];"
                 : "=r"(r[0]), "=r"(r[1]), "=r"(r[2]), "=r"(r[3]) : "r"(a));
}

// pack two fp32 -> bf16x2 (lo in bits [0:16), hi in [16:32))
__device__ __forceinline__ uint32_t pack_bf16x2(float lo, float hi) {
    uint32_t r;
    asm("cvt.rn.bf16x2.f32 %0, %1, %2;" : "=r"(r) : "f"(hi), "f"(lo));
    return r;
}
__device__ __forceinline__ void split2(float v0, float v1, uint32_t& hp, uint32_t& lp) {
    hp = pack_bf16x2(v0, v1);
    float h0 = __uint_as_float(hp << 16);
    float h1 = __uint_as_float(hp & 0xFFFF0000u);
    lp = pack_bf16x2(v0 - h0, v1 - h1);
}

// ---------------------------------------------------------------------------
// Conversion kernels
// ---------------------------------------------------------------------------
__global__ __launch_bounds__(256) void conv_split4_kernel(
    const float* __restrict__ src, __nv_bfloat16* __restrict__ hi,
    __nv_bfloat16* __restrict__ lo, int n4)
{
    int i = blockIdx.x * 256 + threadIdx.x;
    if (i < n4) {
        float4 v = ((const float4*)src)[i];
        uint2 hp, lp;
        split2(v.x, v.y, hp.x, lp.x);
        split2(v.z, v.w, hp.y, lp.y);
        ((uint2*)hi)[i] = hp;
        ((uint2*)lo)[i] = lp;
    }
}

__global__ __launch_bounds__(256) void conv_wqkv_kernel(
    const float* __restrict__ Wq, const float* __restrict__ Wk, const float* __restrict__ Wv)
{
    __shared__ float tile[32][33];
    const int e0 = blockIdx.x * 32;
    const int d0 = blockIdx.y * 32;
    const int z  = blockIdx.z;
    const int which = z / H_, h = z % H_;
    const float* W = (which == 0) ? Wq : (which == 1) ? Wk : Wv;
    W += (size_t)h * E_ * D_;

    const int tx = threadIdx.x & 31, ty = threadIdx.x >> 5;
#pragma unroll
    for (int k = 0; k < 4; k++) {
        int e = e0 + ty + k * 8;
        tile[ty + k * 8][tx] = W[(size_t)e * D_ + d0 + tx];
    }
    __syncthreads();
    const int nbase = which * 1024 + h * 64;
#pragma unroll
    for (int k = 0; k < 4; k++) {
        int d = d0 + ty + k * 8;
        float v = tile[tx][ty + k * 8];
        __nv_bfloat16 hh = __float2bfloat16(v);
        size_t o = (size_t)(nbase + d) * E_ + e0 + tx;
        g_bqh[o] = hh;
        g_bql[o] = __float2bfloat16(v - __bfloat162float(hh));
    }
}

// ---------------------------------------------------------------------------
// Split-bf16 GEMM on mma.sync + ldmatrix fragment loads. KC=64, 2 CTAs/SM.
// Block tile 128x128, 8 warps (2x4), warp tile 64x32.  (R13 — proven 423us)
// ---------------------------------------------------------------------------
#define KC  64
#define LDT 72
#define TILE_E (128 * LDT)
#define GEMM_SMEM_BYTES (4 * TILE_E * 2)    // 72 KB

__global__ __launch_bounds__(256, 2) void gemm_mma_kernel(int mode, const float* __restrict__ bp,
                                                          float* __restrict__ out)
{
    extern __shared__ __nv_bfloat16 smx[];
    __nv_bfloat16* Ah = smx;
    __nv_bfloat16* Al = smx + TILE_E;
    __nv_bfloat16* Bh = smx + 2 * TILE_E;
    __nv_bfloat16* Bl = smx + 3 * TILE_E;

    const int tid  = threadIdx.x;
    const int wid  = tid >> 5;
    const int lane = tid & 31;
    const int wm = wid >> 2;
    const int wn = wid & 3;
    const int group = lane >> 2;
    const int tig   = lane & 3;

    // ldmatrix lane address components
    const int a_row = lane & 15;
    const int a_col = (lane >> 4) * 8;
    const int b_row = (lane & 7) + ((lane >> 4) << 3);
    const int b_col = ((lane >> 3) & 1) * 8;

    const int m0 = blockIdx.x * 128;
    const int n0 = blockIdx.y * 128;

    const __nv_bfloat16 *gAh, *gAl, *gBh, *gBl;
    if (mode == 0) { gAh = g_xh; gAl = g_xl; gBh = g_bqh; gBl = g_bql; }
    else           { gAh = g_ath; gAl = g_atl; gBh = g_wph; gBl = g_wpl; }

    float acc[4][4][4];
#pragma unroll
    for (int mi = 0; mi < 4; mi++)
#pragma unroll
        for (int ni = 0; ni < 4; ni++)
#pragma unroll
            for (int f = 0; f < 4; f++) acc[mi][ni][f] = 0.f;

    for (int e0 = 0; e0 < E_; e0 += KC) {
#pragma unroll
        for (int i = 0; i < 4; i++) {
            int idx = tid + i * 256;
            int r = idx >> 3, q = idx & 7;
            *(uint4*)(Ah + r * LDT + q * 8) = *(const uint4*)(gAh + (size_t)(m0 + r) * E_ + e0 + q * 8);
            *(uint4*)(Al + r * LDT + q * 8) = *(const uint4*)(gAl + (size_t)(m0 + r) * E_ + e0 + q * 8);
            *(uint4*)(Bh + r * LDT + q * 8) = *(const uint4*)(gBh + (size_t)(n0 + r) * E_ + e0 + q * 8);
            *(uint4*)(Bl + r * LDT + q * 8) = *(const uint4*)(gBl + (size_t)(n0 + r) * E_ + e0 + q * 8);
        }
        __syncthreads();

#pragma unroll
        for (int k0 = 0; k0 < KC; k0 += 16) {
            uint32_t ah[4][4], al[4][4];
#pragma unroll
            for (int mi = 0; mi < 4; mi++) {
                const size_t aoff = (size_t)(wm * 64 + mi * 16 + a_row) * LDT + k0 + a_col;
                ldsm4(ah[mi], Ah + aoff);
                ldsm4(al[mi], Al + aoff);
            }
            uint32_t bh4[2][4], bl4[2][4];
#pragma unroll
            for (int np = 0; np < 2; np++) {
                const size_t boff = (size_t)(wn * 32 + np * 16 + b_row) * LDT + k0 + b_col;
                ldsm4(bh4[np], Bh + boff);
                ldsm4(bl4[np], Bl + boff);
            }
#pragma unroll
            for (int ni = 0; ni < 4; ni++) {
                uint32_t bh0 = bh4[ni >> 1][(ni & 1) * 2];
                uint32_t bh1 = bh4[ni >> 1][(ni & 1) * 2 + 1];
                uint32_t bl0 = bl4[ni >> 1][(ni & 1) * 2];
                uint32_t bl1 = bl4[ni >> 1][(ni & 1) * 2 + 1];
#pragma unroll
                for (int mi = 0; mi < 4; mi++) {
                    mma16816(acc[mi][ni], ah[mi], bh0, bh1);
                    mma16816(acc[mi][ni], ah[mi], bl0, bl1);
                    mma16816(acc[mi][ni], al[mi], bh0, bh1);
                }
            }
        }
        __syncthreads();
    }

    // Epilogue
#pragma unroll
    for (int mi = 0; mi < 4; mi++) {
        int row0 = m0 + wm * 64 + mi * 16 + group;
#pragma unroll
        for (int ni = 0; ni < 4; ni++) {
            int nc = n0 + wn * 32 + ni * 8 + tig * 2;
            if (mode == 0) {
                const int which = nc >> 10;
                const int rem = nc & 1023;
                const int h = rem >> 6, d = rem & 63;
                __nv_bfloat16* bash = (which == 0) ? g_qh : (which == 1) ? g_kh : g_vh;
                __nv_bfloat16* basl = (which == 0) ? g_ql : (which == 1) ? g_kl : g_vl;
                const float sc = (which == 0) ? 0.125f : 1.0f;
#pragma unroll
                for (int half = 0; half < 2; half++) {
                    const int row = row0 + half * 8;
                    const int b = row >> 11, t = row & 2047;
                    float v0 = acc[mi][ni][half * 2] * sc;
                    float v1 = acc[mi][ni][half * 2 + 1] * sc;
                    uint32_t hp, lp;
                    split2(v0, v1, hp, lp);
                    size_t off = (((size_t)(b * H_ + h)) * T_ + t) * D_ + d;
                    *(uint32_t*)(bash + off) = hp;
                    *(uint32_t*)(basl + off) = lp;
                }
            } else {
                float2 bias = *(const float2*)(bp + nc);
                float2 v0 = make_float2(acc[mi][ni][0] + bias.x, acc[mi][ni][1] + bias.y);
                float2 v1 = make_float2(acc[mi][ni][2] + bias.x, acc[mi][ni][3] + bias.y);
                *(float2*)(out + (size_t)row0 * E_ + nc) = v0;
                *(float2*)(out + (size_t)(row0 + 8) * E_ + nc) = v1;
            }
        }
    }
}

// ---------------------------------------------------------------------------
// Flash attention on mma.sync, split-bf16, online softmax in registers.
// CTA: 128 q-rows of one (b,h); 8 warps x 16 rows. kv tiles of 64.
// R16: V stored like K ([kv][d], hi/lo planes in ONE shared array) and PV
// B-fragments loaded via ldmatrix.x4.trans — removes the packed-V layout,
// its PRMT unpacks, and the per-tile transpose/pack phase.
// ---------------------------------------------------------------------------
#define LDK 72

__global__ __launch_bounds__(256) void flash_mma_kernel()
{
    __shared__ __nv_bfloat16 Kh[64 * LDK];
    __shared__ __nv_bfloat16 Kl[64 * LDK];
    __shared__ __nv_bfloat16 Vsm[2 * 64 * LDK];   // [Vh | Vl] contiguous
    __nv_bfloat16* Vh = Vsm;
    __nv_bfloat16* Vl = Vsm + 64 * LDK;

    const int tid  = threadIdx.x;
    const int wid  = tid >> 5;
    const int lane = tid & 31;
    const int g  = lane >> 2;
    const int tg = lane & 3;

    // ldmatrix.trans lane address components for V (B operand of PV):
    // matrix m = lane>>3: kv-half = m&1, d-pair half = m>>1; row within = lane&7
    const int v_row = ((lane >> 3) & 1) * 8 + (lane & 7);   // + ks*16
    const int v_col = (lane >> 4) * 8;                      // + ndp*16

    const int qt = blockIdx.x;
    const int h  = blockIdx.y;
    const int b  = blockIdx.z;
    const int bh = b * H_ + h;
    const int q0 = qt * 128;
    const int row_lo = q0 + wid * 16 + g;

    const __nv_bfloat16* gQh = g_qh + (size_t)bh * T_ * D_;
    const __nv_bfloat16* gQl = g_ql + (size_t)bh * T_ * D_;
    const __nv_bfloat16* gKh = g_kh + (size_t)bh * T_ * D_;
    const __nv_bfloat16* gKl = g_kl + (size_t)bh * T_ * D_;
    const __nv_bfloat16* gVh = g_vh + (size_t)bh * T_ * D_;
    const __nv_bfloat16* gVl = g_vl + (size_t)bh * T_ * D_;

    // Preload Q fragments (Q already scaled by 1/sqrt(D))
    uint32_t qh[4][4], ql[4][4];
#pragma unroll
    for (int ks = 0; ks < 4; ks++) {
        int c = ks * 16 + tg * 2;
        qh[ks][0] = *(const uint32_t*)(gQh + (size_t)row_lo * D_ + c);
        qh[ks][1] = *(const uint32_t*)(gQh + (size_t)(row_lo + 8) * D_ + c);
        qh[ks][2] = *(const uint32_t*)(gQh + (size_t)row_lo * D_ + c + 8);
        qh[ks][3] = *(const uint32_t*)(gQh + (size_t)(row_lo + 8) * D_ + c + 8);
        ql[ks][0] = *(const uint32_t*)(gQl + (size_t)row_lo * D_ + c);
        ql[ks][1] = *(const uint32_t*)(gQl + (size_t)(row_lo + 8) * D_ + c);
        ql[ks][2] = *(const uint32_t*)(gQl + (size_t)row_lo * D_ + c + 8);
        ql[ks][3] = *(const uint32_t*)(gQl + (size_t)(row_lo + 8) * D_ + c + 8);
    }

    float m0 = -1e30f, m1 = -1e30f, l0 = 0.f, l1 = 0.f;
    float o[8][4];
#pragma unroll
    for (int nd = 0; nd < 8; nd++)
#pragma unroll
        for (int f = 0; f < 4; f++) o[nd][f] = 0.f;

    const int ntiles = 2 * qt + 2;
    for (int j = 0; j < ntiles; j++) {
        const int kv0 = j * 64;
        // ---- load K and V tiles (64 x 64 bf16 each, hi+lo), same layout ----
#pragma unroll
        for (int i = 0; i < 2; i++) {
            int idx = tid + i * 256;
            int r = idx >> 3, qd = idx & 7;
            *(uint4*)(Kh + r * LDK + qd * 8) =
                *(const uint4*)(gKh + (size_t)(kv0 + r) * D_ + qd * 8);
            *(uint4*)(Kl + r * LDK + qd * 8) =
                *(const uint4*)(gKl + (size_t)(kv0 + r) * D_ + qd * 8);
            *(uint4*)(Vh + r * LDK + qd * 8) =
                *(const uint4*)(gVh + (size_t)(kv0 + r) * D_ + qd * 8);
            *(uint4*)(Vl + r * LDK + qd * 8) =
                *(const uint4*)(gVl + (size_t)(kv0 + r) * D_ + qd * 8);
        }
        __syncthreads();

        // ---- S = Q K^T (split 3-MMA), scalar K fragment loads ----
        float s[8][4];
#pragma unroll
        for (int nf = 0; nf < 8; nf++)
#pragma unroll
            for (int f = 0; f < 4; f++) s[nf][f] = 0.f;
#pragma unroll
        for (int ks = 0; ks < 4; ks++) {
            int c = ks * 16 + tg * 2;
#pragma unroll
            for (int nf = 0; nf < 8; nf++) {
                int br = nf * 8 + g;
                uint32_t bh0 = *(const uint32_t*)(Kh + br * LDK + c);
                uint32_t bh1 = *(const uint32_t*)(Kh + br * LDK + c + 8);
                uint32_t bl0 = *(const uint32_t*)(Kl + br * LDK + c);
                uint32_t bl1 = *(const uint32_t*)(Kl + br * LDK + c + 8);
                mma16816(s[nf], qh[ks], bh0, bh1);
                mma16816(s[nf], qh[ks], bl0, bl1);
                mma16816(s[nf], ql[ks], bh0, bh1);
            }
        }

        // ---- causal mask ----
        if (j >= ntiles - 2) {
#pragma unroll
            for (int nf = 0; nf < 8; nf++) {
                int col = kv0 + nf * 8 + tg * 2;
                if (col > row_lo)     s[nf][0] = -1e30f;
                if (col + 1 > row_lo) s[nf][1] = -1e30f;
                if (col > row_lo + 8)     s[nf][2] = -1e30f;
                if (col + 1 > row_lo + 8) s[nf][3] = -1e30f;
            }
        }

        // ---- online softmax ----
        float mx0 = -1e30f, mx1 = -1e30f;
#pragma unroll
        for (int nf = 0; nf < 8; nf++) {
            mx0 = fmaxf(mx0, fmaxf(s[nf][0], s[nf][1]));
            mx1 = fmaxf(mx1, fmaxf(s[nf][2], s[nf][3]));
        }
        mx0 = fmaxf(mx0, __shfl_xor_sync(0xffffffff, mx0, 1));
        mx0 = fmaxf(mx0, __shfl_xor_sync(0xffffffff, mx0, 2));
        mx1 = fmaxf(mx1, __shfl_xor_sync(0xffffffff, mx1, 1));
        mx1 = fmaxf(mx1, __shfl_xor_sync(0xffffffff, mx1, 2));
        float mn0 = fmaxf(m0, mx0), mn1 = fmaxf(m1, mx1);
        float c0 = __expf(m0 - mn0), c1 = __expf(m1 - mn1);
        m0 = mn0; m1 = mn1;

        uint32_t ph[4][4], pl[4][4];
        float sum0 = 0.f, sum1 = 0.f;
#pragma unroll
        for (int nf = 0; nf < 8; nf++) {
            float p0 = __expf(s[nf][0] - mn0);
            float p1 = __expf(s[nf][1] - mn0);
            float p2 = __expf(s[nf][2] - mn1);
            float p3 = __expf(s[nf][3] - mn1);
            sum0 += p0 + p1;
            sum1 += p2 + p3;
            int ks = nf >> 1, rr = (nf & 1) * 2;
            split2(p0, p1, ph[ks][rr], pl[ks][rr]);
            split2(p2, p3, ph[ks][rr + 1], pl[ks][rr + 1]);
        }
        sum0 += __shfl_xor_sync(0xffffffff, sum0, 1);
        sum0 += __shfl_xor_sync(0xffffffff, sum0, 2);
        sum1 += __shfl_xor_sync(0xffffffff, sum1, 1);
        sum1 += __shfl_xor_sync(0xffffffff, sum1, 2);
        l0 = l0 * c0 + sum0;
        l1 = l1 * c1 + sum1;

#pragma unroll
        for (int nd = 0; nd < 8; nd++) {
            o[nd][0] *= c0; o[nd][1] *= c0;
            o[nd][2] *= c1; o[nd][3] *= c1;
        }

        // ---- O += P V (split 3-MMA), V fragments via ldmatrix.trans ----
#pragma unroll
        for (int ks = 0; ks < 4; ks++) {
#pragma unroll
            for (int ndp = 0; ndp < 4; ndp++) {
                const size_t voff = (size_t)(ks * 16 + v_row) * LDK + ndp * 16 + v_col;
                uint32_t vbh[4], vbl[4];
                ldsm4t(vbh, Vh + voff);
                ldsm4t(vbl, Vl + voff);
#pragma unroll
                for (int half = 0; half < 2; half++) {
                    int nd = ndp * 2 + half;
                    uint32_t vh0 = vbh[half * 2], vh1 = vbh[half * 2 + 1];
                    uint32_t vl0 = vbl[half * 2], vl1 = vbl[half * 2 + 1];
                    mma16816(o[nd], ph[ks], vh0, vh1);
                    mma16816(o[nd], ph[ks], vl0, vl1);
                    mma16816(o[nd], pl[ks], vh0, vh1);
                }
            }
        }
        __syncthreads();
    }

    // ---- epilogue ----
    float i0 = 1.f / l0, i1 = 1.f / l1;
#pragma unroll
    for (int nd = 0; nd < 8; nd++) {
        int dcol = h * 64 + nd * 8 + tg * 2;
        const int grow0 = b * T_ + row_lo;
        const int grow1 = grow0 + 8;
        uint32_t hp, lp;
        split2(o[nd][0] * i0, o[nd][1] * i0, hp, lp);
        *(uint32_t*)(g_ath + (size_t)grow0 * E_ + dcol) = hp;
        *(uint32_t*)(g_atl + (size_t)grow0 * E_ + dcol) = lp;
        split2(o[nd][2] * i1, o[nd][3] * i1, hp, lp);
        *(uint32_t*)(g_ath + (size_t)grow1 * E_ + dcol) = hp;
        *(uint32_t*)(g_atl + (size_t)grow1 * E_ + dcol) = lp;
    }
}

// ---------------------------------------------------------------------------
extern "C" void kernel_launch(void* const* d_in, const int* in_sizes, int n_in,
                              void* d_out, int out_size)
{
    const float* x  = (const float*)d_in[0];
    const float* Wq = (const float*)d_in[1];
    const float* Wk = (const float*)d_in[2];
    const float* Wv = (const float*)d_in[3];
    const float* Wp = (const float*)d_in[4];
    const float* bp = (const float*)d_in[5];
    float* out = (float*)d_out;

    cudaFuncSetAttribute(gemm_mma_kernel,
                         cudaFuncAttributeMaxDynamicSharedMemorySize, GEMM_SMEM_BYTES);

    __nv_bfloat16 *xh, *xl, *wph, *wpl;
    cudaGetSymbolAddress((void**)&xh,  g_xh);
    cudaGetSymbolAddress((void**)&xl,  g_xl);
    cudaGetSymbolAddress((void**)&wph, g_wph);
    cudaGetSymbolAddress((void**)&wpl, g_wpl);

    // 1) split-convert x and weights
    conv_split4_kernel<<<(M_TOTAL * E_ / 4 + 255) / 256, 256>>>(x, xh, xl, M_TOTAL * E_ / 4);
    conv_wqkv_kernel<<<dim3(E_ / 32, D_ / 32, 3 * H_), 256>>>(Wq, Wk, Wv);
    conv_split4_kernel<<<(E_ * E_ / 4 + 255) / 256, 256>>>(Wp, wph, wpl, E_ * E_ / 4);

    // 2) QKV projection -> split-bf16 q/k/v (Q pre-scaled)
    gemm_mma_kernel<<<dim3(M_TOTAL / 128, NQKV / 128), 256, GEMM_SMEM_BYTES>>>(0, nullptr, nullptr);

    // 3) causal flash attention on tensor cores -> g_ath/g_atl
    flash_mma_kernel<<<dim3(T_ / 128, H_, B_), 256>>>();

    // 4) output projection
    gemm_mma_kernel<<<dim3(M_TOTAL / 128, E_ / 128), 256, GEMM_SMEM_BYTES>>>(1, bp, out);
}

// round 17
// speedup vs baseline: 1.1300x; 1.0509x over previous
#include <cuda_runtime.h>
#include <cuda_bf16.h>
#include <cstdint>

// Problem constants
#define B_  4
#define T_  2048
#define E_  1024
#define H_  16
#define D_  64

#define M_TOTAL (B_ * T_)          // 8192
#define NQKV    (3 * H_ * D_)      // 3072

// ---------------------------------------------------------------------------
// Scratch (__device__ globals: allocation-free rule)
// ---------------------------------------------------------------------------
__device__ __nv_bfloat16 g_qh[B_ * H_ * T_ * D_];
__device__ __nv_bfloat16 g_ql[B_ * H_ * T_ * D_];
__device__ __nv_bfloat16 g_kh[B_ * H_ * T_ * D_];
__device__ __nv_bfloat16 g_kl[B_ * H_ * T_ * D_];
__device__ __nv_bfloat16 g_vh[B_ * H_ * T_ * D_];
__device__ __nv_bfloat16 g_vl[B_ * H_ * T_ * D_];

__device__ __nv_bfloat16 g_xh[M_TOTAL * E_];
__device__ __nv_bfloat16 g_xl[M_TOTAL * E_];
__device__ __nv_bfloat16 g_bqh[NQKV * E_];
__device__ __nv_bfloat16 g_bql[NQKV * E_];
__device__ __nv_bfloat16 g_wph[E_ * E_];
__device__ __nv_bfloat16 g_wpl[E_ * E_];
__device__ __nv_bfloat16 g_ath[M_TOTAL * E_];
__device__ __nv_bfloat16 g_atl[M_TOTAL * E_];

// ---------------------------------------------------------------------------
// Helpers
// ---------------------------------------------------------------------------
__device__ __forceinline__ void mma16816(float c[4], const uint32_t a[4],
                                         uint32_t b0, uint32_t b1) {
    asm volatile(
        "mma.sync.aligned.m16n8k16.row.col.f32.bf16.bf16.f32 "
        "{%0,%1,%2,%3}, {%4,%5,%6,%7}, {%8,%9}, {%0,%1,%2,%3};"
        : "+f"(c[0]), "+f"(c[1]), "+f"(c[2]), "+f"(c[3])
        : "r"(a[0]), "r"(a[1]), "r"(a[2]), "r"(a[3]), "r"(b0), "r"(b1));
}

__device__ __forceinline__ void ldsm4(uint32_t r[4], const void* p) {
    uint32_t a = (uint32_t)__cvta_generic_to_shared(p);
    asm volatile("ldmatrix.sync.aligned.m8n8.x4.shared.b16 {%0,%1,%2,%3}, [%4];"
                 : "=r"(r[0]), "=r"(r[1]), "=r"(r[2]), "=r"(r[3]) : "r"(a));
}
__device__ __forceinline__ void ldsm4t(uint32_t r[4], const void* p) {
    uint32_t a = (uint32_t)__cvta_generic_to_shared(p);
    asm volatile("ldmatrix.sync.aligned.m8n8.x4.trans.shared.b16 {%0,%1,%2,%3}, [%4];"
                 : "=r"(r[0]), "=r"(r[1]), "=r"(r[2]), "=r"(r[3]) : "r"(a));
}

// pack two fp32 -> bf16x2 (lo in bits [0:16), hi in [16:32))
__device__ __forceinline__ uint32_t pack_bf16x2(float lo, float hi) {
    uint32_t r;
    asm("cvt.rn.bf16x2.f32 %0, %1, %2;" : "=r"(r) : "f"(hi), "f"(lo));
    return r;
}
__device__ __forceinline__ void split2(float v0, float v1, uint32_t& hp, uint32_t& lp) {
    hp = pack_bf16x2(v0, v1);
    float h0 = __uint_as_float(hp << 16);
    float h1 = __uint_as_float(hp & 0xFFFF0000u);
    lp = pack_bf16x2(v0 - h0, v1 - h1);
}

// ---------------------------------------------------------------------------
// Conversion kernels
// ---------------------------------------------------------------------------
__global__ __launch_bounds__(256) void conv_split4_kernel(
    const float* __restrict__ src, __nv_bfloat16* __restrict__ hi,
    __nv_bfloat16* __restrict__ lo, int n4)
{
    int i = blockIdx.x * 256 + threadIdx.x;
    if (i < n4) {
        float4 v = ((const float4*)src)[i];
        uint2 hp, lp;
        split2(v.x, v.y, hp.x, lp.x);
        split2(v.z, v.w, hp.y, lp.y);
        ((uint2*)hi)[i] = hp;
        ((uint2*)lo)[i] = lp;
    }
}

__global__ __launch_bounds__(256) void conv_wqkv_kernel(
    const float* __restrict__ Wq, const float* __restrict__ Wk, const float* __restrict__ Wv)
{
    __shared__ float tile[32][33];
    const int e0 = blockIdx.x * 32;
    const int d0 = blockIdx.y * 32;
    const int z  = blockIdx.z;
    const int which = z / H_, h = z % H_;
    const float* W = (which == 0) ? Wq : (which == 1) ? Wk : Wv;
    W += (size_t)h * E_ * D_;

    const int tx = threadIdx.x & 31, ty = threadIdx.x >> 5;
#pragma unroll
    for (int k = 0; k < 4; k++) {
        int e = e0 + ty + k * 8;
        tile[ty + k * 8][tx] = W[(size_t)e * D_ + d0 + tx];
    }
    __syncthreads();
    const int nbase = which * 1024 + h * 64;
#pragma unroll
    for (int k = 0; k < 4; k++) {
        int d = d0 + ty + k * 8;
        float v = tile[tx][ty + k * 8];
        __nv_bfloat16 hh = __float2bfloat16(v);
        size_t o = (size_t)(nbase + d) * E_ + e0 + tx;
        g_bqh[o] = hh;
        g_bql[o] = __float2bfloat16(v - __bfloat162float(hh));
    }
}

// ---------------------------------------------------------------------------
// Split-bf16 GEMM on mma.sync + ldmatrix fragment loads. KC=64, 2 CTAs/SM.
// Block tile 128x128, 8 warps (2x4), warp tile 64x32.  (R13 — proven 423us)
// ---------------------------------------------------------------------------
#define KC  64
#define LDT 72
#define TILE_E (128 * LDT)
#define GEMM_SMEM_BYTES (4 * TILE_E * 2)    // 72 KB

__global__ __launch_bounds__(256, 2) void gemm_mma_kernel(int mode, const float* __restrict__ bp,
                                                          float* __restrict__ out)
{
    extern __shared__ __nv_bfloat16 smx[];
    __nv_bfloat16* Ah = smx;
    __nv_bfloat16* Al = smx + TILE_E;
    __nv_bfloat16* Bh = smx + 2 * TILE_E;
    __nv_bfloat16* Bl = smx + 3 * TILE_E;

    const int tid  = threadIdx.x;
    const int wid  = tid >> 5;
    const int lane = tid & 31;
    const int wm = wid >> 2;
    const int wn = wid & 3;
    const int group = lane >> 2;
    const int tig   = lane & 3;

    // ldmatrix lane address components
    const int a_row = lane & 15;
    const int a_col = (lane >> 4) * 8;
    const int b_row = (lane & 7) + ((lane >> 4) << 3);
    const int b_col = ((lane >> 3) & 1) * 8;

    const int m0 = blockIdx.x * 128;
    const int n0 = blockIdx.y * 128;

    const __nv_bfloat16 *gAh, *gAl, *gBh, *gBl;
    if (mode == 0) { gAh = g_xh; gAl = g_xl; gBh = g_bqh; gBl = g_bql; }
    else           { gAh = g_ath; gAl = g_atl; gBh = g_wph; gBl = g_wpl; }

    float acc[4][4][4];
#pragma unroll
    for (int mi = 0; mi < 4; mi++)
#pragma unroll
        for (int ni = 0; ni < 4; ni++)
#pragma unroll
            for (int f = 0; f < 4; f++) acc[mi][ni][f] = 0.f;

    for (int e0 = 0; e0 < E_; e0 += KC) {
#pragma unroll
        for (int i = 0; i < 4; i++) {
            int idx = tid + i * 256;
            int r = idx >> 3, q = idx & 7;
            *(uint4*)(Ah + r * LDT + q * 8) = *(const uint4*)(gAh + (size_t)(m0 + r) * E_ + e0 + q * 8);
            *(uint4*)(Al + r * LDT + q * 8) = *(const uint4*)(gAl + (size_t)(m0 + r) * E_ + e0 + q * 8);
            *(uint4*)(Bh + r * LDT + q * 8) = *(const uint4*)(gBh + (size_t)(n0 + r) * E_ + e0 + q * 8);
            *(uint4*)(Bl + r * LDT + q * 8) = *(const uint4*)(gBl + (size_t)(n0 + r) * E_ + e0 + q * 8);
        }
        __syncthreads();

#pragma unroll
        for (int k0 = 0; k0 < KC; k0 += 16) {
            uint32_t ah[4][4], al[4][4];
#pragma unroll
            for (int mi = 0; mi < 4; mi++) {
                const size_t aoff = (size_t)(wm * 64 + mi * 16 + a_row) * LDT + k0 + a_col;
                ldsm4(ah[mi], Ah + aoff);
                ldsm4(al[mi], Al + aoff);
            }
            uint32_t bh4[2][4], bl4[2][4];
#pragma unroll
            for (int np = 0; np < 2; np++) {
                const size_t boff = (size_t)(wn * 32 + np * 16 + b_row) * LDT + k0 + b_col;
                ldsm4(bh4[np], Bh + boff);
                ldsm4(bl4[np], Bl + boff);
            }
#pragma unroll
            for (int ni = 0; ni < 4; ni++) {
                uint32_t bh0 = bh4[ni >> 1][(ni & 1) * 2];
                uint32_t bh1 = bh4[ni >> 1][(ni & 1) * 2 + 1];
                uint32_t bl0 = bl4[ni >> 1][(ni & 1) * 2];
                uint32_t bl1 = bl4[ni >> 1][(ni & 1) * 2 + 1];
#pragma unroll
                for (int mi = 0; mi < 4; mi++) {
                    mma16816(acc[mi][ni], ah[mi], bh0, bh1);
                    mma16816(acc[mi][ni], ah[mi], bl0, bl1);
                    mma16816(acc[mi][ni], al[mi], bh0, bh1);
                }
            }
        }
        __syncthreads();
    }

    // Epilogue
#pragma unroll
    for (int mi = 0; mi < 4; mi++) {
        int row0 = m0 + wm * 64 + mi * 16 + group;
#pragma unroll
        for (int ni = 0; ni < 4; ni++) {
            int nc = n0 + wn * 32 + ni * 8 + tig * 2;
            if (mode == 0) {
                const int which = nc >> 10;
                const int rem = nc & 1023;
                const int h = rem >> 6, d = rem & 63;
                __nv_bfloat16* bash = (which == 0) ? g_qh : (which == 1) ? g_kh : g_vh;
                __nv_bfloat16* basl = (which == 0) ? g_ql : (which == 1) ? g_kl : g_vl;
                const float sc = (which == 0) ? 0.125f : 1.0f;
#pragma unroll
                for (int half = 0; half < 2; half++) {
                    const int row = row0 + half * 8;
                    const int b = row >> 11, t = row & 2047;
                    float v0 = acc[mi][ni][half * 2] * sc;
                    float v1 = acc[mi][ni][half * 2 + 1] * sc;
                    uint32_t hp, lp;
                    split2(v0, v1, hp, lp);
                    size_t off = (((size_t)(b * H_ + h)) * T_ + t) * D_ + d;
                    *(uint32_t*)(bash + off) = hp;
                    *(uint32_t*)(basl + off) = lp;
                }
            } else {
                float2 bias = *(const float2*)(bp + nc);
                float2 v0 = make_float2(acc[mi][ni][0] + bias.x, acc[mi][ni][1] + bias.y);
                float2 v1 = make_float2(acc[mi][ni][2] + bias.x, acc[mi][ni][3] + bias.y);
                *(float2*)(out + (size_t)row0 * E_ + nc) = v0;
                *(float2*)(out + (size_t)(row0 + 8) * E_ + nc) = v1;
            }
        }
    }
}

// ---------------------------------------------------------------------------
// Flash attention on mma.sync, split-bf16, online softmax in registers.
// CTA: 128 q-rows of one (b,h); 8 warps x 16 rows. kv tiles of 64.
// R16 V-path via ldmatrix.trans; R17: __launch_bounds__(256, 2) — the packed-V
// register machinery is gone, so the 128-reg cap should now fit, and the
// co-resident CTA's MMA bursts cover load/softmax phases (R11 mechanism).
// ---------------------------------------------------------------------------
#define LDK 72

__global__ __launch_bounds__(256, 2) void flash_mma_kernel()
{
    __shared__ __nv_bfloat16 Kh[64 * LDK];
    __shared__ __nv_bfloat16 Kl[64 * LDK];
    __shared__ __nv_bfloat16 Vsm[2 * 64 * LDK];   // [Vh | Vl] contiguous
    __nv_bfloat16* Vh = Vsm;
    __nv_bfloat16* Vl = Vsm + 64 * LDK;

    const int tid  = threadIdx.x;
    const int wid  = tid >> 5;
    const int lane = tid & 31;
    const int g  = lane >> 2;
    const int tg = lane & 3;

    // ldmatrix.trans lane address components for V (B operand of PV)
    const int v_row = ((lane >> 3) & 1) * 8 + (lane & 7);   // + ks*16
    const int v_col = (lane >> 4) * 8;                      // + ndp*16

    const int qt = blockIdx.x;
    const int h  = blockIdx.y;
    const int b  = blockIdx.z;
    const int bh = b * H_ + h;
    const int q0 = qt * 128;
    const int row_lo = q0 + wid * 16 + g;

    const __nv_bfloat16* gQh = g_qh + (size_t)bh * T_ * D_;
    const __nv_bfloat16* gQl = g_ql + (size_t)bh * T_ * D_;
    const __nv_bfloat16* gKh = g_kh + (size_t)bh * T_ * D_;
    const __nv_bfloat16* gKl = g_kl + (size_t)bh * T_ * D_;
    const __nv_bfloat16* gVh = g_vh + (size_t)bh * T_ * D_;
    const __nv_bfloat16* gVl = g_vl + (size_t)bh * T_ * D_;

    // Preload Q fragments (Q already scaled by 1/sqrt(D))
    uint32_t qh[4][4], ql[4][4];
#pragma unroll
    for (int ks = 0; ks < 4; ks++) {
        int c = ks * 16 + tg * 2;
        qh[ks][0] = *(const uint32_t*)(gQh + (size_t)row_lo * D_ + c);
        qh[ks][1] = *(const uint32_t*)(gQh + (size_t)(row_lo + 8) * D_ + c);
        qh[ks][2] = *(const uint32_t*)(gQh + (size_t)row_lo * D_ + c + 8);
        qh[ks][3] = *(const uint32_t*)(gQh + (size_t)(row_lo + 8) * D_ + c + 8);
        ql[ks][0] = *(const uint32_t*)(gQl + (size_t)row_lo * D_ + c);
        ql[ks][1] = *(const uint32_t*)(gQl + (size_t)(row_lo + 8) * D_ + c);
        ql[ks][2] = *(const uint32_t*)(gQl + (size_t)row_lo * D_ + c + 8);
        ql[ks][3] = *(const uint32_t*)(gQl + (size_t)(row_lo + 8) * D_ + c + 8);
    }

    float m0 = -1e30f, m1 = -1e30f, l0 = 0.f, l1 = 0.f;
    float o[8][4];
#pragma unroll
    for (int nd = 0; nd < 8; nd++)
#pragma unroll
        for (int f = 0; f < 4; f++) o[nd][f] = 0.f;

    const int ntiles = 2 * qt + 2;
    for (int j = 0; j < ntiles; j++) {
        const int kv0 = j * 64;
        // ---- load K and V tiles (64 x 64 bf16 each, hi+lo), same layout ----
#pragma unroll
        for (int i = 0; i < 2; i++) {
            int idx = tid + i * 256;
            int r = idx >> 3, qd = idx & 7;
            *(uint4*)(Kh + r * LDK + qd * 8) =
                *(const uint4*)(gKh + (size_t)(kv0 + r) * D_ + qd * 8);
            *(uint4*)(Kl + r * LDK + qd * 8) =
                *(const uint4*)(gKl + (size_t)(kv0 + r) * D_ + qd * 8);
            *(uint4*)(Vh + r * LDK + qd * 8) =
                *(const uint4*)(gVh + (size_t)(kv0 + r) * D_ + qd * 8);
            *(uint4*)(Vl + r * LDK + qd * 8) =
                *(const uint4*)(gVl + (size_t)(kv0 + r) * D_ + qd * 8);
        }
        __syncthreads();

        // ---- S = Q K^T (split 3-MMA), scalar K fragment loads ----
        float s[8][4];
#pragma unroll
        for (int nf = 0; nf < 8; nf++)
#pragma unroll
            for (int f = 0; f < 4; f++) s[nf][f] = 0.f;
#pragma unroll
        for (int ks = 0; ks < 4; ks++) {
            int c = ks * 16 + tg * 2;
#pragma unroll
            for (int nf = 0; nf < 8; nf++) {
                int br = nf * 8 + g;
                uint32_t bh0 = *(const uint32_t*)(Kh + br * LDK + c);
                uint32_t bh1 = *(const uint32_t*)(Kh + br * LDK + c + 8);
                uint32_t bl0 = *(const uint32_t*)(Kl + br * LDK + c);
                uint32_t bl1 = *(const uint32_t*)(Kl + br * LDK + c + 8);
                mma16816(s[nf], qh[ks], bh0, bh1);
                mma16816(s[nf], qh[ks], bl0, bl1);
                mma16816(s[nf], ql[ks], bh0, bh1);
            }
        }

        // ---- causal mask ----
        if (j >= ntiles - 2) {
#pragma unroll
            for (int nf = 0; nf < 8; nf++) {
                int col = kv0 + nf * 8 + tg * 2;
                if (col > row_lo)     s[nf][0] = -1e30f;
                if (col + 1 > row_lo) s[nf][1] = -1e30f;
                if (col > row_lo + 8)     s[nf][2] = -1e30f;
                if (col + 1 > row_lo + 8) s[nf][3] = -1e30f;
            }
        }

        // ---- online softmax ----
        float mx0 = -1e30f, mx1 = -1e30f;
#pragma unroll
        for (int nf = 0; nf < 8; nf++) {
            mx0 = fmaxf(mx0, fmaxf(s[nf][0], s[nf][1]));
            mx1 = fmaxf(mx1, fmaxf(s[nf][2], s[nf][3]));
        }
        mx0 = fmaxf(mx0, __shfl_xor_sync(0xffffffff, mx0, 1));
        mx0 = fmaxf(mx0, __shfl_xor_sync(0xffffffff, mx0, 2));
        mx1 = fmaxf(mx1, __shfl_xor_sync(0xffffffff, mx1, 1));
        mx1 = fmaxf(mx1, __shfl_xor_sync(0xffffffff, mx1, 2));
        float mn0 = fmaxf(m0, mx0), mn1 = fmaxf(m1, mx1);
        float c0 = __expf(m0 - mn0), c1 = __expf(m1 - mn1);
        m0 = mn0; m1 = mn1;

        uint32_t ph[4][4], pl[4][4];
        float sum0 = 0.f, sum1 = 0.f;
#pragma unroll
        for (int nf = 0; nf < 8; nf++) {
            float p0 = __expf(s[nf][0] - mn0);
            float p1 = __expf(s[nf][1] - mn0);
            float p2 = __expf(s[nf][2] - mn1);
            float p3 = __expf(s[nf][3] - mn1);
            sum0 += p0 + p1;
            sum1 += p2 + p3;
            int ks = nf >> 1, rr = (nf & 1) * 2;
            split2(p0, p1, ph[ks][rr], pl[ks][rr]);
            split2(p2, p3, ph[ks][rr + 1], pl[ks][rr + 1]);
        }
        sum0 += __shfl_xor_sync(0xffffffff, sum0, 1);
        sum0 += __shfl_xor_sync(0xffffffff, sum0, 2);
        sum1 += __shfl_xor_sync(0xffffffff, sum1, 1);
        sum1 += __shfl_xor_sync(0xffffffff, sum1, 2);
        l0 = l0 * c0 + sum0;
        l1 = l1 * c1 + sum1;

#pragma unroll
        for (int nd = 0; nd < 8; nd++) {
            o[nd][0] *= c0; o[nd][1] *= c0;
            o[nd][2] *= c1; o[nd][3] *= c1;
        }

        // ---- O += P V (split 3-MMA), V fragments via ldmatrix.trans ----
#pragma unroll
        for (int ks = 0; ks < 4; ks++) {
#pragma unroll
            for (int ndp = 0; ndp < 4; ndp++) {
                const size_t voff = (size_t)(ks * 16 + v_row) * LDK + ndp * 16 + v_col;
                uint32_t vbh[4], vbl[4];
                ldsm4t(vbh, Vh + voff);
                ldsm4t(vbl, Vl + voff);
#pragma unroll
                for (int half = 0; half < 2; half++) {
                    int nd = ndp * 2 + half;
                    uint32_t vh0 = vbh[half * 2], vh1 = vbh[half * 2 + 1];
                    uint32_t vl0 = vbl[half * 2], vl1 = vbl[half * 2 + 1];
                    mma16816(o[nd], ph[ks], vh0, vh1);
                    mma16816(o[nd], ph[ks], vl0, vl1);
                    mma16816(o[nd], pl[ks], vh0, vh1);
                }
            }
        }
        __syncthreads();
    }

    // ---- epilogue ----
    float i0 = 1.f / l0, i1 = 1.f / l1;
#pragma unroll
    for (int nd = 0; nd < 8; nd++) {
        int dcol = h * 64 + nd * 8 + tg * 2;
        const int grow0 = b * T_ + row_lo;
        const int grow1 = grow0 + 8;
        uint32_t hp, lp;
        split2(o[nd][0] * i0, o[nd][1] * i0, hp, lp);
        *(uint32_t*)(g_ath + (size_t)grow0 * E_ + dcol) = hp;
        *(uint32_t*)(g_atl + (size_t)grow0 * E_ + dcol) = lp;
        split2(o[nd][2] * i1, o[nd][3] * i1, hp, lp);
        *(uint32_t*)(g_ath + (size_t)grow1 * E_ + dcol) = hp;
        *(uint32_t*)(g_atl + (size_t)grow1 * E_ + dcol) = lp;
    }
}

// ---------------------------------------------------------------------------
extern "C" void kernel_launch(void* const* d_in, const int* in_sizes, int n_in,
                              void* d_out, int out_size)
{
    const float* x  = (const float*)d_in[0];
    const float* Wq = (const float*)d_in[1];
    const float* Wk = (const float*)d_in[2];
    const float* Wv = (const float*)d_in[3];
    const float* Wp = (const float*)d_in[4];
    const float* bp = (const float*)d_in[5];
    float* out = (float*)d_out;

    cudaFuncSetAttribute(gemm_mma_kernel,
                         cudaFuncAttributeMaxDynamicSharedMemorySize, GEMM_SMEM_BYTES);

    __nv_bfloat16 *xh, *xl, *wph, *wpl;
    cudaGetSymbolAddress((void**)&xh,  g_xh);
    cudaGetSymbolAddress((void**)&xl,  g_xl);
    cudaGetSymbolAddress((void**)&wph, g_wph);
    cudaGetSymbolAddress((void**)&wpl, g_wpl);

    // 1) split-convert x and weights
    conv_split4_kernel<<<(M_TOTAL * E_ / 4 + 255) / 256, 256>>>(x, xh, xl, M_TOTAL * E_ / 4);
    conv_wqkv_kernel<<<dim3(E_ / 32, D_ / 32, 3 * H_), 256>>>(Wq, Wk, Wv);
    conv_split4_kernel<<<(E_ * E_ / 4 + 255) / 256, 256>>>(Wp, wph, wpl, E_ * E_ / 4);

    // 2) QKV projection -> split-bf16 q/k/v (Q pre-scaled)
    gemm_mma_kernel<<<dim3(M_TOTAL / 128, NQKV / 128), 256, GEMM_SMEM_BYTES>>>(0, nullptr, nullptr);

    // 3) causal flash attention on tensor cores -> g_ath/g_atl
    flash_mma_kernel<<<dim3(T_ / 128, H_, B_), 256>>>();

    // 4) output projection
    gemm_mma_kernel<<<dim3(M_TOTAL / 128, E_ / 128), 256, GEMM_SMEM_BYTES>>>(1, bp, out);
}